// round 5
// baseline (speedup 1.0000x reference)
#include <cuda_runtime.h>

#define BB 8
#define NNROWS 4000
#define CC 80
#define NC (NNROWS*CC)        // 320000
#define KPRE 2048
#define DETN 100
#define NWORDS (KPRE/64)      // 32
#define CAP 8192
#define CLIPF 4.135166556742356f

// ---------------- device scratch (static, no allocation) ----------------
__device__ unsigned long long g_keys[BB][NC];          // 20.5 MB
__device__ unsigned int       g_hist16[BB][65536];     // 2 MB
__device__ unsigned int       g_prefix16[BB];
__device__ int                g_above[BB];
__device__ int                g_k2[BB];
__device__ int                g_cntA[BB];
__device__ int                g_cntC[BB];
__device__ int                g_cnt2[BB];
__device__ unsigned long long g_cand[BB][CAP];         // 512 KB
__device__ unsigned long long g_topkeys[BB][KPRE];
__device__ float              g_scores[BB][KPRE];
__device__ float4             g_boxes[BB][KPRE];
__device__ float4             g_nmsb[BB][KPRE];
__device__ int                g_labels[BB][KPRE];
__device__ int                g_vcount[BB];
__device__ unsigned long long g_mask[BB][KPRE][NWORDS]; // 4 MB

// ---------------- helpers ----------------
__device__ __forceinline__ unsigned f2ord(float f) {
    unsigned u = __float_as_uint(f);
    return (u & 0x80000000u) ? ~u : (u | 0x80000000u);
}
__device__ __forceinline__ float ord2f(unsigned o) {
    unsigned u = (o & 0x80000000u) ? (o ^ 0x80000000u) : ~o;
    return __uint_as_float(u);
}

__device__ __forceinline__ void decode_box(float d0, float d1, float d2, float d3,
                                           float4 p,
                                           float& x1, float& y1, float& x2, float& y2) {
    float w  = p.z - p.x;
    float h  = p.w - p.y;
    float cx = p.x + 0.5f * w;
    float cy = p.y + 0.5f * h;
    float dx = d0 / 10.0f;
    float dy = d1 / 10.0f;
    float dw = fminf(d2 / 5.0f, CLIPF);
    float dh = fminf(d3 / 5.0f, CLIPF);
    float pcx = dx * w + cx;
    float pcy = dy * h + cy;
    float pw  = expf(dw) * w;
    float ph  = expf(dh) * h;
    x1 = pcx - 0.5f * pw;
    y1 = pcy - 0.5f * ph;
    x2 = pcx + 0.5f * pw;
    y2 = pcy + 0.5f * ph;
}

// ---------------- kernels ----------------
__global__ void k_init() {
    int t = blockIdx.x * blockDim.x + threadIdx.x;
    int H = BB * 65536;
    unsigned* h = (unsigned*)g_hist16;
    for (int i = t; i < H; i += gridDim.x * blockDim.x) h[i] = 0u;
    if (t < BB) { g_cntA[t] = 0; g_cntC[t] = 0; g_cnt2[t] = 0; }
}

// one warp per proposal row: softmax, per-class decode for validity, emit keys + 16-bit hist
__global__ __launch_bounds__(256) void k_scorekey(const float* __restrict__ label,
                                                  const float* __restrict__ bbox,
                                                  const float* __restrict__ props) {
    int img  = blockIdx.y;
    int warp = threadIdx.x >> 5;
    int lane = threadIdx.x & 31;
    int row  = blockIdx.x * 8 + warp;
    if (row >= NNROWS) return;

    const float* L = label + ((size_t)img * NNROWS + row) * (CC + 1);

    float m = -3.402823466e38f;
    for (int c = lane; c < CC + 1; c += 32) m = fmaxf(m, L[c]);
#pragma unroll
    for (int o = 16; o > 0; o >>= 1) m = fmaxf(m, __shfl_xor_sync(0xffffffffu, m, o));

    float ssum = 0.0f;
    for (int c = lane; c < CC + 1; c += 32) ssum += expf(L[c] - m);
#pragma unroll
    for (int o = 16; o > 0; o >>= 1) ssum += __shfl_xor_sync(0xffffffffu, ssum, o);

    float4 p = ((const float4*)props)[img * NNROWS + row];
    const float4* D4 = (const float4*)(bbox + ((size_t)img * NNROWS + row) * ((CC + 1) * 4) + 4);

    for (int c = lane; c < CC; c += 32) {
        float sc = expf(L[c + 1] - m) / ssum;
        float4 d = D4[c];
        float x1, y1, x2, y2;
        decode_box(d.x, d.y, d.z, d.w, p, x1, y1, x2, y2);
        float area = (y2 - y1) * (x2 - x1);
        float masked = ((sc > 0.01f) && (area > 0.1f)) ? sc : -1.0f;
        unsigned idx = (unsigned)(row * CC + c);
        unsigned ordv = f2ord(masked);
        unsigned long long key =
            ((unsigned long long)ordv << 32) | (unsigned long long)(0xFFFFFFFFu - idx);
        g_keys[img][idx] = key;

        // warp-aggregated histogram atomic (invalid keys all share one bin)
        unsigned bin = ordv >> 16;
        unsigned am = __activemask();
        unsigned peers = __match_any_sync(am, bin);
        int leader = __ffs(peers) - 1;
        if (lane == leader)
            atomicAdd(&g_hist16[img][bin], (unsigned)__popc(peers));
    }
}

// one block per image: find 16-bit pivot bucket
__global__ __launch_bounds__(256) void k_select16() {
    int img = blockIdx.x;
    int t = threadIdx.x;
    __shared__ unsigned csum[256];
    __shared__ int stc;
    __shared__ unsigned sacc;
    __shared__ unsigned sb[256];

    unsigned s = 0;
    const unsigned* h = &g_hist16[img][t * 256];
#pragma unroll 8
    for (int i = 0; i < 256; i++) s += h[i];
    csum[t] = s;
    __syncthreads();

    if (t == 0) {
        unsigned acc = 0; int tc = 0;
        bool found = false;
#pragma unroll 8
        for (int u = 255; u >= 0; --u) {
            unsigned c = csum[u];
            if (!found) {
                if (acc + c >= KPRE) { tc = u; found = true; }
                else acc += c;
            }
        }
        stc = tc; sacc = acc;
    }
    __syncthreads();
    int tc = stc;
    sb[t] = g_hist16[img][tc * 256 + t];
    __syncthreads();

    if (t == 0) {
        unsigned acc = sacc; int b = 0;
        bool found = false;
#pragma unroll 8
        for (int dd = 255; dd >= 0; --dd) {
            unsigned c = sb[dd];
            if (!found) {
                if (acc + c >= KPRE) { b = dd; found = true; }
                else acc += c;
            }
        }
        g_prefix16[img] = (unsigned)(tc * 256 + b);
        g_above[img] = (int)acc;
        g_k2[img] = KPRE - (int)acc;
    }
}

__global__ __launch_bounds__(256) void k_compact() {
    int img = blockIdx.y;
    unsigned prefix = g_prefix16[img];
    for (int i = blockIdx.x * blockDim.x + threadIdx.x; i < NC; i += gridDim.x * blockDim.x) {
        unsigned long long key = g_keys[img][i];
        unsigned p16 = (unsigned)(key >> 48);
        if (p16 > prefix) {
            int p = atomicAdd(&g_cntA[img], 1);
            g_topkeys[img][p] = key;
        } else if (p16 == prefix) {
            int p = atomicAdd(&g_cntC[img], 1);
            if (p < CAP) g_cand[img][p] = key;
        }
    }
}

// exact 64-bit pivot among bucket candidates, append top-k2 to g_topkeys
__global__ __launch_bounds__(256) void k_refine() {
    int img = blockIdx.x;
    int t = threadIdx.x;
    __shared__ unsigned hist[256];
    __shared__ unsigned long long spfx;
    __shared__ int sk;

    int n = g_cntC[img]; if (n > CAP) n = CAP;
    if (t == 0) {
        spfx = (unsigned long long)g_prefix16[img] << 48;
        sk = g_k2[img];
    }
    __syncthreads();

    for (int r = 0; r < 6; r++) {
        int sh = 40 - 8 * r;
        hist[t] = 0;
        __syncthreads();
        unsigned long long hi_mask = ~((1ull << (sh + 8)) - 1ull);
        unsigned long long pfx = spfx;
        for (int i = t; i < n; i += 256) {
            unsigned long long key = g_cand[img][i];
            if ((key & hi_mask) == pfx)
                atomicAdd(&hist[(unsigned)(key >> sh) & 0xFFu], 1u);
        }
        __syncthreads();
        if (t == 0) {
            int k = sk, acc = 0, d = 0;
            bool found = false;
#pragma unroll 8
            for (int dd = 255; dd >= 0; --dd) {
                int c = (int)hist[dd];
                if (!found) {
                    if (acc + c >= k) { d = dd; found = true; }
                    else acc += c;
                }
            }
            spfx |= ((unsigned long long)d) << sh;
            sk = k - acc;
        }
        __syncthreads();
    }

    unsigned long long pivot = spfx;
    int above = g_above[img];
    for (int i = t; i < n; i += 256) {
        unsigned long long key = g_cand[img][i];
        if (key >= pivot) {
            int p = above + atomicAdd(&g_cnt2[img], 1);
            g_topkeys[img][p] = key;
        }
    }
}

// sort 2048 keys descending (bitonic on complemented keys), decode selected boxes
__global__ __launch_bounds__(1024) void k_sortdecode(const float* __restrict__ bbox,
                                                     const float* __restrict__ props) {
    int img = blockIdx.x;
    int tid = threadIdx.x;
    __shared__ unsigned long long s[KPRE];
    s[tid]        = ~g_topkeys[img][tid];
    s[tid + 1024] = ~g_topkeys[img][tid + 1024];
    __syncthreads();

    for (int ksz = 2; ksz <= KPRE; ksz <<= 1) {
        for (int j = ksz >> 1; j > 0; j >>= 1) {
            for (int i = tid; i < KPRE; i += 1024) {
                int ixj = i ^ j;
                if (ixj > i) {
                    unsigned long long a = s[i], b = s[ixj];
                    bool up = ((i & ksz) == 0);
                    if ((a > b) == up) { s[i] = b; s[ixj] = a; }
                }
            }
            __syncthreads();
        }
    }

    for (int i = tid; i < KPRE; i += 1024) {
        unsigned long long key = ~s[i];
        float sc = ord2f((unsigned)(key >> 32));
        unsigned idx = 0xFFFFFFFFu - (unsigned)(key & 0xFFFFFFFFull);
        int n = (int)(idx / CC);
        int c = (int)(idx - (unsigned)n * CC);
        float4 p = ((const float4*)props)[img * NNROWS + n];
        const float4* D4 = (const float4*)(bbox + ((size_t)img * NNROWS + n) * ((CC + 1) * 4) + 4);
        float4 d = D4[c];
        float x1, y1, x2, y2;
        decode_box(d.x, d.y, d.z, d.w, p, x1, y1, x2, y2);
        g_scores[img][i] = sc;
        g_boxes[img][i]  = make_float4(x1, y1, x2, y2);
        float off = (float)(c + 1) * 4096.0f;
        g_nmsb[img][i]   = make_float4(x1 + off, y1 + off, x2 + off, y2 + off);
        g_labels[img][i] = c + 1;

        float nx = (i < KPRE - 1) ? ord2f((unsigned)((~s[i + 1]) >> 32)) : -2.0f;
        if (i == 0 && !(sc > 0.0f)) g_vcount[img] = 0;
        if (sc > 0.0f && (i == KPRE - 1 || !(nx > 0.0f))) g_vcount[img] = i + 1;
    }
}

__global__ __launch_bounds__(64) void k_mask() {
    int img = blockIdx.z;
    int bx  = blockIdx.x;   // col chunk
    int by  = blockIdx.y;   // row chunk
    int t   = threadIdx.x;
    __shared__ float4 cb[64];
    cb[t] = g_nmsb[img][bx * 64 + t];
    __syncthreads();

    int row = by * 64 + t;
    float4 a = g_nmsb[img][row];
    float aw = fmaxf(a.z - a.x, 0.0f), ah = fmaxf(a.w - a.y, 0.0f);
    float areaA = aw * ah;

    unsigned long long bits = 0ull;
#pragma unroll 8
    for (int j = 0; j < 64; j++) {
        int col = bx * 64 + j;
        if (col > row) {
            float4 b = cb[j];
            float bw = fmaxf(b.z - b.x, 0.0f), bh = fmaxf(b.w - b.y, 0.0f);
            float areaB = bw * bh;
            float w = fmaxf(fminf(a.z, b.z) - fmaxf(a.x, b.x), 0.0f);
            float h = fmaxf(fminf(a.w, b.w) - fmaxf(a.y, b.y), 0.0f);
            float inter = w * h;
            float uni = areaA + areaB - inter;
            if (inter / fmaxf(uni, 1e-9f) > 0.5f) bits |= (1ull << j);
        }
    }
    g_mask[img][row][bx] = bits;
}

__global__ __launch_bounds__(128) void k_reduceout(float* __restrict__ out) {
    int img = blockIdx.x;
    int tid = threadIdx.x;
    __shared__ unsigned long long skeep[NWORDS];
    __shared__ int sdet[DETN];
    __shared__ int sdetk[DETN];

    if (tid < 32) {
        int V = g_vcount[img];
        int base = tid * 64;
        unsigned long long rm;
        if (V <= base)           rm = ~0ull;
        else if (V >= base + 64) rm = 0ull;
        else                     rm = (~0ull) << (V - base);

        unsigned long long nxt = g_mask[img][0][tid];
        for (int i = 0; i < KPRE; i++) {
            unsigned long long cur = nxt;
            if (i + 1 < KPRE) nxt = g_mask[img][i + 1][tid];
            unsigned long long w = __shfl_sync(0xffffffffu, rm, i >> 6);
            if (!((w >> (i & 63)) & 1ull)) rm |= cur;
        }
        skeep[tid] = ~rm;
    }
    __syncthreads();

    if (tid == 0) {
        int nk = 0;
        for (int i = 0; i < KPRE && nk < DETN; i++)
            if ((skeep[i >> 6] >> (i & 63)) & 1ull) { sdet[nk] = i; sdetk[nk] = 1; nk++; }
        for (int i = 0; i < KPRE && nk < DETN; i++)
            if (!((skeep[i >> 6] >> (i & 63)) & 1ull)) { sdet[nk] = i; sdetk[nk] = 0; nk++; }
    }
    __syncthreads();

    if (tid < DETN) {
        int i = sdet[tid];
        float4 b = g_boxes[img][i];
        int o = img * DETN + tid;
        out[o * 4 + 0] = b.x;
        out[o * 4 + 1] = b.y;
        out[o * 4 + 2] = b.z;
        out[o * 4 + 3] = b.w;
        out[BB * DETN * 4 + o] = sdetk[tid] ? g_scores[img][i] : -1.0f;
        out[BB * DETN * 5 + o] = (float)g_labels[img][i];
    }
}

// ---------------- launch ----------------
extern "C" void kernel_launch(void* const* d_in, const int* in_sizes, int n_in,
                              void* d_out, int out_size) {
    const float* label = (const float*)d_in[0];
    const float* bbox  = (const float*)d_in[1];
    const float* props = (const float*)d_in[2];
    float* out = (float*)d_out;

    k_init<<<512, 256>>>();
    k_scorekey<<<dim3(500, BB), 256>>>(label, bbox, props);
    k_select16<<<BB, 256>>>();
    k_compact<<<dim3(128, BB), 256>>>();
    k_refine<<<BB, 256>>>();
    k_sortdecode<<<BB, 1024>>>(bbox, props);
    k_mask<<<dim3(32, 32, BB), 64>>>();
    k_reduceout<<<BB, 128>>>(out);
}

// round 6
// speedup vs baseline: 1.5811x; 1.5811x over previous
#include <cuda_runtime.h>

#define BB 8
#define NNROWS 4000
#define CC 80
#define NC (NNROWS*CC)        // 320000
#define KPRE 2048
#define SRT 4096
#define DETN 100
#define NWORDS (KPRE/64)      // 32
#define CLIPF 4.135166556742356f
#define INVBIN 0x407Fu        // f2ord(-1.0f) >> 16

// ---------------- device scratch (static, no allocation) ----------------
__device__ unsigned long long g_keys[BB][NC];          // 20.5 MB
__device__ unsigned int       g_hist16[BB][65536];     // 2 MB
__device__ unsigned int       g_prefix16[BB];
__device__ int                g_cnt[BB];
__device__ unsigned long long g_all[BB][SRT];          // 256 KB (zero-padded)
__device__ float              g_scores[BB][KPRE];
__device__ float4             g_boxes[BB][KPRE];
__device__ float4             g_nmsb[BB][KPRE];
__device__ int                g_labels[BB][KPRE];
__device__ int                g_vcount[BB];

// ---------------- helpers ----------------
__device__ __forceinline__ unsigned f2ord(float f) {
    unsigned u = __float_as_uint(f);
    return (u & 0x80000000u) ? ~u : (u | 0x80000000u);
}
__device__ __forceinline__ float ord2f(unsigned o) {
    unsigned u = (o & 0x80000000u) ? (o ^ 0x80000000u) : ~o;
    return __uint_as_float(u);
}

__device__ __forceinline__ void decode_box(float d0, float d1, float d2, float d3,
                                           float4 p,
                                           float& x1, float& y1, float& x2, float& y2) {
    float w  = p.z - p.x;
    float h  = p.w - p.y;
    float cx = p.x + 0.5f * w;
    float cy = p.y + 0.5f * h;
    float dx = d0 / 10.0f;
    float dy = d1 / 10.0f;
    float dw = fminf(d2 / 5.0f, CLIPF);
    float dh = fminf(d3 / 5.0f, CLIPF);
    float pcx = dx * w + cx;
    float pcy = dy * h + cy;
    float pw  = expf(dw) * w;
    float ph  = expf(dh) * h;
    x1 = pcx - 0.5f * pw;
    y1 = pcy - 0.5f * ph;
    x2 = pcx + 0.5f * pw;
    y2 = pcy + 0.5f * ph;
}

// ---------------- kernels ----------------
__global__ void k_init() {
    int t = blockIdx.x * blockDim.x + threadIdx.x;
    int stride = gridDim.x * blockDim.x;
    unsigned* h = (unsigned*)g_hist16;
    for (int i = t; i < BB * 65536; i += stride) h[i] = 0u;
    unsigned long long* a = (unsigned long long*)g_all;
    for (int i = t; i < BB * SRT; i += stride) a[i] = 0ull;
    if (t < BB) g_cnt[t] = 0;
}

// one warp per proposal row: softmax, per-class decode for validity, emit keys + 16-bit hist
__global__ __launch_bounds__(256) void k_scorekey(const float* __restrict__ label,
                                                  const float* __restrict__ bbox,
                                                  const float* __restrict__ props) {
    int img  = blockIdx.y;
    int warp = threadIdx.x >> 5;
    int lane = threadIdx.x & 31;
    int row  = blockIdx.x * 8 + warp;
    if (row >= NNROWS) return;

    const float* L = label + ((size_t)img * NNROWS + row) * (CC + 1);

    float m = -3.402823466e38f;
    for (int c = lane; c < CC + 1; c += 32) m = fmaxf(m, L[c]);
#pragma unroll
    for (int o = 16; o > 0; o >>= 1) m = fmaxf(m, __shfl_xor_sync(0xffffffffu, m, o));

    float ssum = 0.0f;
    for (int c = lane; c < CC + 1; c += 32) ssum += expf(L[c] - m);
#pragma unroll
    for (int o = 16; o > 0; o >>= 1) ssum += __shfl_xor_sync(0xffffffffu, ssum, o);

    float4 p = ((const float4*)props)[img * NNROWS + row];
    const float4* D4 = (const float4*)(bbox + ((size_t)img * NNROWS + row) * ((CC + 1) * 4) + 4);

    int invc = 0;
    for (int c = lane; c < CC; c += 32) {
        float sc = expf(L[c + 1] - m) / ssum;
        float4 d = D4[c];
        float x1, y1, x2, y2;
        decode_box(d.x, d.y, d.z, d.w, p, x1, y1, x2, y2);
        float area = (y2 - y1) * (x2 - x1);
        bool valid = (sc > 0.01f) && (area > 0.1f);
        float masked = valid ? sc : -1.0f;
        unsigned idx = (unsigned)(row * CC + c);
        unsigned ordv = f2ord(masked);
        g_keys[img][idx] =
            ((unsigned long long)ordv << 32) | (unsigned long long)(0xFFFFFFFFu - idx);
        if (valid) atomicAdd(&g_hist16[img][ordv >> 16], 1u);
        else invc++;
    }
#pragma unroll
    for (int o = 16; o > 0; o >>= 1) invc += __shfl_xor_sync(0xffffffffu, invc, o);
    if (lane == 0 && invc) atomicAdd(&g_hist16[img][INVBIN], (unsigned)invc);
}

// one block per image: find 16-bit pivot bucket (coalesced reads)
__global__ __launch_bounds__(256) void k_select16() {
    int img = blockIdx.x;
    int t = threadIdx.x;
    int w = t >> 5, lane = t & 31;
    __shared__ unsigned csum[256];
    __shared__ unsigned sb[256];
    __shared__ int stc;
    __shared__ unsigned sacc;

    // 256 chunk sums, warp-cooperative (coalesced)
    for (int c = w; c < 256; c += 8) {
        const unsigned* h = &g_hist16[img][c * 256];
        unsigned s = 0;
#pragma unroll
        for (int k = 0; k < 8; k++) s += h[lane + 32 * k];
#pragma unroll
        for (int o = 16; o > 0; o >>= 1) s += __shfl_xor_sync(0xffffffffu, s, o);
        if (lane == 0) csum[c] = s;
    }
    __syncthreads();

    if (t == 0) {
        unsigned acc = 0; int tc = 0;
        for (int c = 255; c >= 0; --c) {
            unsigned cc = csum[c];
            if (acc + cc >= KPRE) { tc = c; break; }
            acc += cc;
        }
        stc = tc; sacc = acc;
    }
    __syncthreads();
    sb[t] = g_hist16[img][stc * 256 + t];
    __syncthreads();
    if (t == 0) {
        unsigned acc = sacc; int b = 0;
        for (int dd = 255; dd >= 0; --dd) {
            unsigned c = sb[dd];
            if (acc + c >= KPRE) { b = dd; break; }
            acc += c;
        }
        g_prefix16[img] = (unsigned)(stc * 256 + b);
    }
}

// single pass: every key whose 16-bit prefix >= pivot bucket goes to g_all
__global__ __launch_bounds__(256) void k_compact() {
    int img = blockIdx.y;
    unsigned prefix = g_prefix16[img];
    for (int i = blockIdx.x * blockDim.x + threadIdx.x; i < NC; i += gridDim.x * blockDim.x) {
        unsigned long long key = g_keys[img][i];
        if ((unsigned)(key >> 48) >= prefix) {
            int p = atomicAdd(&g_cnt[img], 1);
            if (p < SRT) g_all[img][p] = key;
        }
    }
}

// sort 4096 (zero-padded) keys descending, decode top 2048
__global__ __launch_bounds__(1024) void k_sortdecode(const float* __restrict__ bbox,
                                                     const float* __restrict__ props) {
    int img = blockIdx.x;
    int tid = threadIdx.x;
    __shared__ unsigned long long s[SRT];
    for (int i = tid; i < SRT; i += 1024) s[i] = ~g_all[img][i];
    __syncthreads();

    for (int ksz = 2; ksz <= SRT; ksz <<= 1) {
        for (int j = ksz >> 1; j > 0; j >>= 1) {
            for (int i = tid; i < SRT; i += 1024) {
                int ixj = i ^ j;
                if (ixj > i) {
                    unsigned long long a = s[i], b = s[ixj];
                    bool up = ((i & ksz) == 0);
                    if ((a > b) == up) { s[i] = b; s[ixj] = a; }
                }
            }
            __syncthreads();
        }
    }

    for (int i = tid; i < KPRE; i += 1024) {
        unsigned long long key = ~s[i];
        float sc = ord2f((unsigned)(key >> 32));
        unsigned idx = 0xFFFFFFFFu - (unsigned)(key & 0xFFFFFFFFull);
        int n = (int)(idx / CC);
        int c = (int)(idx - (unsigned)n * CC);
        float4 p = ((const float4*)props)[img * NNROWS + n];
        const float4* D4 = (const float4*)(bbox + ((size_t)img * NNROWS + n) * ((CC + 1) * 4) + 4);
        float4 d = D4[c];
        float x1, y1, x2, y2;
        decode_box(d.x, d.y, d.z, d.w, p, x1, y1, x2, y2);
        g_scores[img][i] = sc;
        g_boxes[img][i]  = make_float4(x1, y1, x2, y2);
        float off = (float)(c + 1) * 4096.0f;
        g_nmsb[img][i]   = make_float4(x1 + off, y1 + off, x2 + off, y2 + off);
        g_labels[img][i] = c + 1;

        if (i == 0 && !(sc > 0.0f)) g_vcount[img] = 0;
        if (sc > 0.0f) {
            if (i == KPRE - 1) g_vcount[img] = KPRE;
            else {
                float nx = ord2f((unsigned)((~s[i + 1]) >> 32));
                if (!(nx > 0.0f)) g_vcount[img] = i + 1;
            }
        }
    }
}

// lazy greedy NMS against kept list + early exit at DETN keeps + output
__global__ __launch_bounds__(32) void k_nmsout(float* __restrict__ out) {
    int img  = blockIdx.x;
    int lane = threadIdx.x;
    __shared__ float4 cache[512];
    __shared__ float4 kb[DETN];
    __shared__ int    ki[DETN];
    __shared__ unsigned long long keepm[NWORDS];
    __shared__ int sdet[DETN];
    __shared__ int sflag[DETN];

    for (int i = lane; i < 512; i += 32) cache[i] = g_nmsb[img][i];
    if (lane < NWORDS) keepm[lane] = 0ull;
    int V = g_vcount[img];
    __syncwarp();

    int nk = 0;
    for (int i = 0; i < V && nk < DETN; i++) {
        float4 a = (i < 512) ? cache[i] : g_nmsb[img][i];
        float aw = fmaxf(a.z - a.x, 0.0f), ah = fmaxf(a.w - a.y, 0.0f);
        float areaA = aw * ah;
        bool sup = false;
        for (int j = lane; j < nk; j += 32) {
            float4 b = kb[j];
            float bw = fmaxf(b.z - b.x, 0.0f), bh = fmaxf(b.w - b.y, 0.0f);
            float w = fmaxf(fminf(a.z, b.z) - fmaxf(a.x, b.x), 0.0f);
            float h = fmaxf(fminf(a.w, b.w) - fmaxf(a.y, b.y), 0.0f);
            float inter = w * h;
            float uni = areaA + bw * bh - inter;
            if (inter / fmaxf(uni, 1e-9f) > 0.5f) sup = true;
        }
        if (!__any_sync(0xffffffffu, sup)) {
            if (lane == 0) {
                kb[nk] = a;
                ki[nk] = i;
                keepm[i >> 6] |= (1ull << (i & 63));
            }
            __syncwarp();
            nk++;
        }
    }

    if (lane == 0) {
        int c = 0;
        for (int q = 0; q < nk && c < DETN; q++) { sdet[c] = ki[q]; sflag[c] = 1; c++; }
        for (int i = 0; i < KPRE && c < DETN; i++)
            if (!((keepm[i >> 6] >> (i & 63)) & 1ull)) { sdet[c] = i; sflag[c] = 0; c++; }
    }
    __syncwarp();

    for (int t = lane; t < DETN; t += 32) {
        int i = sdet[t];
        float4 b = g_boxes[img][i];
        int o = img * DETN + t;
        out[o * 4 + 0] = b.x;
        out[o * 4 + 1] = b.y;
        out[o * 4 + 2] = b.z;
        out[o * 4 + 3] = b.w;
        out[BB * DETN * 4 + o] = sflag[t] ? g_scores[img][i] : -1.0f;
        out[BB * DETN * 5 + o] = (float)g_labels[img][i];
    }
}

// ---------------- launch ----------------
extern "C" void kernel_launch(void* const* d_in, const int* in_sizes, int n_in,
                              void* d_out, int out_size) {
    const float* label = (const float*)d_in[0];
    const float* bbox  = (const float*)d_in[1];
    const float* props = (const float*)d_in[2];
    float* out = (float*)d_out;

    k_init<<<512, 256>>>();
    k_scorekey<<<dim3(500, BB), 256>>>(label, bbox, props);
    k_select16<<<BB, 256>>>();
    k_compact<<<dim3(256, BB), 256>>>();
    k_sortdecode<<<BB, 1024>>>(bbox, props);
    k_nmsout<<<BB, 32>>>(out);
}

// round 7
// speedup vs baseline: 1.7941x; 1.1348x over previous
#include <cuda_runtime.h>

#define BB 8
#define NNROWS 4000
#define CC 80
#define NC (NNROWS*CC)        // 320000
#define KPRE 2048
#define SRT 4096
#define DETN 100
#define NWORDS (KPRE/64)      // 32
#define CLIPF 4.135166556742356f
#define INVBIN 0x407Fu        // f2ord(-1.0f) >> 16

// ---------------- device scratch (static, no allocation) ----------------
__device__ unsigned int       g_ord[BB][NC];           // 10.25 MB
__device__ unsigned int       g_hist16[BB][65536];     // 2 MB
__device__ unsigned int       g_prefix16[BB];
__device__ int                g_cnt[BB];
__device__ unsigned long long g_all[BB][SRT];          // 256 KB (zero-padded)
__device__ float              g_scores[BB][KPRE];
__device__ float4             g_boxes[BB][KPRE];
__device__ float4             g_nmsb[BB][KPRE];
__device__ int                g_labels[BB][KPRE];
__device__ int                g_vcount[BB];

// ---------------- helpers ----------------
__device__ __forceinline__ unsigned f2ord(float f) {
    unsigned u = __float_as_uint(f);
    return (u & 0x80000000u) ? ~u : (u | 0x80000000u);
}
__device__ __forceinline__ float ord2f(unsigned o) {
    unsigned u = (o & 0x80000000u) ? (o ^ 0x80000000u) : ~o;
    return __uint_as_float(u);
}

__device__ __forceinline__ void decode_box(float d0, float d1, float d2, float d3,
                                           float4 p,
                                           float& x1, float& y1, float& x2, float& y2) {
    float w  = p.z - p.x;
    float h  = p.w - p.y;
    float cx = p.x + 0.5f * w;
    float cy = p.y + 0.5f * h;
    float dx = d0 / 10.0f;
    float dy = d1 / 10.0f;
    float dw = fminf(d2 / 5.0f, CLIPF);
    float dh = fminf(d3 / 5.0f, CLIPF);
    float pcx = dx * w + cx;
    float pcy = dy * h + cy;
    float pw  = expf(dw) * w;
    float ph  = expf(dh) * h;
    x1 = pcx - 0.5f * pw;
    y1 = pcy - 0.5f * ph;
    x2 = pcx + 0.5f * pw;
    y2 = pcy + 0.5f * ph;
}

// ---------------- kernels ----------------
__global__ void k_init() {
    int t = blockIdx.x * blockDim.x + threadIdx.x;
    int stride = gridDim.x * blockDim.x;
    unsigned* h = (unsigned*)g_hist16;
    for (int i = t; i < BB * 65536; i += stride) h[i] = 0u;
    unsigned long long* a = (unsigned long long*)g_all;
    for (int i = t; i < BB * SRT; i += stride) a[i] = 0ull;
    if (t < BB) g_cnt[t] = 0;
}

// one warp per proposal row: softmax (exps computed once, rotated via shfl),
// validity with single-exp area test, 32-bit ord emission + 16-bit hist
__global__ __launch_bounds__(256) void k_scorekey(const float* __restrict__ label,
                                                  const float* __restrict__ bbox,
                                                  const float* __restrict__ props) {
    int img  = blockIdx.y;
    int warp = threadIdx.x >> 5;
    int lane = threadIdx.x & 31;
    int row  = blockIdx.x * 8 + warp;
    if (row >= NNROWS) return;

    const float* L = label + ((size_t)img * NNROWS + row) * (CC + 1);

    float l0 = L[lane];
    float l1 = L[lane + 32];
    float l2 = (lane < 17) ? L[lane + 64] : -3.402823466e38f;

    float m = fmaxf(fmaxf(l0, l1), l2);
#pragma unroll
    for (int o = 16; o > 0; o >>= 1) m = fmaxf(m, __shfl_xor_sync(0xffffffffu, m, o));

    float e0 = __expf(l0 - m);
    float e1 = __expf(l1 - m);
    float e2 = (lane < 17) ? __expf(l2 - m) : 0.0f;

    float ssum = e0 + e1 + e2;
#pragma unroll
    for (int o = 16; o > 0; o >>= 1) ssum += __shfl_xor_sync(0xffffffffu, ssum, o);
    float inv = 1.0f / ssum;

    // rotate: lane needs exp of class (c+1) for candidates c = lane, lane+32, lane+64
    int src = (lane + 1) & 31;
    float a  = __shfl_sync(0xffffffffu, e0, src);
    float b  = __shfl_sync(0xffffffffu, e1, src);
    float cv = __shfl_sync(0xffffffffu, e2, src);
    float sc0 = ((lane < 31) ? a : b) * inv;    // class lane+1
    float sc1 = ((lane < 31) ? b : cv) * inv;   // class lane+33
    float sc2 = cv * inv;                        // class lane+65 (lane<16)

    float4 p = ((const float4*)props)[img * NNROWS + row];
    float w  = p.z - p.x;
    float h  = p.w - p.y;
    float wh = w * h;
    const float4* D4 = (const float4*)(bbox + ((size_t)img * NNROWS + row) * ((CC + 1) * 4) + 4);
    unsigned* O = &g_ord[img][row * CC];

    int invc = 0;
#pragma unroll
    for (int k = 0; k < 3; k++) {
        int c = lane + 32 * k;
        if (c >= CC) break;
        float sc = (k == 0) ? sc0 : (k == 1) ? sc1 : sc2;
        bool valid = false;
        if (sc > 0.01f) {
            float4 d = D4[c];
            float dw = fminf(d.z / 5.0f, CLIPF);
            float dh = fminf(d.w / 5.0f, CLIPF);
            float area = __expf(dw + dh) * wh;
            valid = (area > 0.1f);
        }
        unsigned ordv;
        if (valid) {
            ordv = f2ord(sc);
            atomicAdd(&g_hist16[img][ordv >> 16], 1u);
        } else {
            ordv = (INVBIN << 16) | 0xFFFFu;   // f2ord(-1.0f)
            invc++;
        }
        O[c] = ordv;
    }
#pragma unroll
    for (int o = 16; o > 0; o >>= 1) invc += __shfl_xor_sync(0xffffffffu, invc, o);
    if (lane == 0 && invc) atomicAdd(&g_hist16[img][INVBIN], (unsigned)invc);
}

// one block per image: find 16-bit pivot bucket (coalesced reads)
__global__ __launch_bounds__(256) void k_select16() {
    int img = blockIdx.x;
    int t = threadIdx.x;
    int w = t >> 5, lane = t & 31;
    __shared__ unsigned csum[256];
    __shared__ unsigned sb[256];
    __shared__ int stc;
    __shared__ unsigned sacc;

    for (int c = w; c < 256; c += 8) {
        const unsigned* h = &g_hist16[img][c * 256];
        unsigned s = 0;
#pragma unroll
        for (int k = 0; k < 8; k++) s += h[lane + 32 * k];
#pragma unroll
        for (int o = 16; o > 0; o >>= 1) s += __shfl_xor_sync(0xffffffffu, s, o);
        if (lane == 0) csum[c] = s;
    }
    __syncthreads();

    if (t == 0) {
        unsigned acc = 0; int tc = 0;
        for (int c = 255; c >= 0; --c) {
            unsigned cc = csum[c];
            if (acc + cc >= KPRE) { tc = c; break; }
            acc += cc;
        }
        stc = tc; sacc = acc;
    }
    __syncthreads();
    sb[t] = g_hist16[img][stc * 256 + t];
    __syncthreads();
    if (t == 0) {
        unsigned acc = sacc; int b = 0;
        for (int dd = 255; dd >= 0; --dd) {
            unsigned c = sb[dd];
            if (acc + c >= KPRE) { b = dd; break; }
            acc += c;
        }
        g_prefix16[img] = (unsigned)(stc * 256 + b);
    }
}

// single pass over 32-bit ords (uint4-vectorized); reconstruct 64-bit keys for winners
__global__ __launch_bounds__(256) void k_compact() {
    int img = blockIdx.y;
    unsigned prefix = g_prefix16[img];
    const uint4* src = (const uint4*)g_ord[img];
    int n4 = NC / 4;
    for (int i = blockIdx.x * blockDim.x + threadIdx.x; i < n4; i += gridDim.x * blockDim.x) {
        uint4 v = src[i];
        unsigned base = (unsigned)(i * 4);
#pragma unroll
        for (int k = 0; k < 4; k++) {
            unsigned ordv = (k == 0) ? v.x : (k == 1) ? v.y : (k == 2) ? v.z : v.w;
            if ((ordv >> 16) >= prefix) {
                int p = atomicAdd(&g_cnt[img], 1);
                if (p < SRT) {
                    unsigned idx = base + k;
                    g_all[img][p] = ((unsigned long long)ordv << 32)
                                  | (unsigned long long)(0xFFFFFFFFu - idx);
                }
            }
        }
    }
}

// sort 4096 (zero-padded) keys descending, decode top 2048 (precise expf)
__global__ __launch_bounds__(1024) void k_sortdecode(const float* __restrict__ bbox,
                                                     const float* __restrict__ props) {
    int img = blockIdx.x;
    int tid = threadIdx.x;
    __shared__ unsigned long long s[SRT];
    for (int i = tid; i < SRT; i += 1024) s[i] = ~g_all[img][i];
    __syncthreads();

    for (int ksz = 2; ksz <= SRT; ksz <<= 1) {
        for (int j = ksz >> 1; j > 0; j >>= 1) {
            for (int i = tid; i < SRT; i += 1024) {
                int ixj = i ^ j;
                if (ixj > i) {
                    unsigned long long a = s[i], b = s[ixj];
                    bool up = ((i & ksz) == 0);
                    if ((a > b) == up) { s[i] = b; s[ixj] = a; }
                }
            }
            __syncthreads();
        }
    }

    for (int i = tid; i < KPRE; i += 1024) {
        unsigned long long key = ~s[i];
        float sc = ord2f((unsigned)(key >> 32));
        unsigned idx = 0xFFFFFFFFu - (unsigned)(key & 0xFFFFFFFFull);
        int n = (int)(idx / CC);
        int c = (int)(idx - (unsigned)n * CC);
        float4 p = ((const float4*)props)[img * NNROWS + n];
        const float4* D4 = (const float4*)(bbox + ((size_t)img * NNROWS + n) * ((CC + 1) * 4) + 4);
        float4 d = D4[c];
        float x1, y1, x2, y2;
        decode_box(d.x, d.y, d.z, d.w, p, x1, y1, x2, y2);
        g_scores[img][i] = sc;
        g_boxes[img][i]  = make_float4(x1, y1, x2, y2);
        float off = (float)(c + 1) * 4096.0f;
        g_nmsb[img][i]   = make_float4(x1 + off, y1 + off, x2 + off, y2 + off);
        g_labels[img][i] = c + 1;

        if (i == 0 && !(sc > 0.0f)) g_vcount[img] = 0;
        if (sc > 0.0f) {
            if (i == KPRE - 1) g_vcount[img] = KPRE;
            else {
                float nx = ord2f((unsigned)((~s[i + 1]) >> 32));
                if (!(nx > 0.0f)) g_vcount[img] = i + 1;
            }
        }
    }
}

// lazy greedy NMS against kept list + early exit at DETN keeps + output
__global__ __launch_bounds__(32) void k_nmsout(float* __restrict__ out) {
    int img  = blockIdx.x;
    int lane = threadIdx.x;
    __shared__ float4 cache[512];
    __shared__ float4 kb[DETN];
    __shared__ int    ki[DETN];
    __shared__ unsigned long long keepm[NWORDS];
    __shared__ int sdet[DETN];
    __shared__ int sflag[DETN];

    for (int i = lane; i < 512; i += 32) cache[i] = g_nmsb[img][i];
    if (lane < NWORDS) keepm[lane] = 0ull;
    int V = g_vcount[img];
    __syncwarp();

    int nk = 0;
    for (int i = 0; i < V && nk < DETN; i++) {
        float4 a = (i < 512) ? cache[i] : g_nmsb[img][i];
        float aw = fmaxf(a.z - a.x, 0.0f), ah = fmaxf(a.w - a.y, 0.0f);
        float areaA = aw * ah;
        bool sup = false;
        for (int j = lane; j < nk; j += 32) {
            float4 b = kb[j];
            float bw = fmaxf(b.z - b.x, 0.0f), bh = fmaxf(b.w - b.y, 0.0f);
            float w = fmaxf(fminf(a.z, b.z) - fmaxf(a.x, b.x), 0.0f);
            float h = fmaxf(fminf(a.w, b.w) - fmaxf(a.y, b.y), 0.0f);
            float inter = w * h;
            float uni = areaA + bw * bh - inter;
            if (inter / fmaxf(uni, 1e-9f) > 0.5f) sup = true;
        }
        if (!__any_sync(0xffffffffu, sup)) {
            if (lane == 0) {
                kb[nk] = a;
                ki[nk] = i;
                keepm[i >> 6] |= (1ull << (i & 63));
            }
            __syncwarp();
            nk++;
        }
    }

    if (lane == 0) {
        int c = 0;
        for (int q = 0; q < nk && c < DETN; q++) { sdet[c] = ki[q]; sflag[c] = 1; c++; }
        for (int i = 0; i < KPRE && c < DETN; i++)
            if (!((keepm[i >> 6] >> (i & 63)) & 1ull)) { sdet[c] = i; sflag[c] = 0; c++; }
    }
    __syncwarp();

    for (int t = lane; t < DETN; t += 32) {
        int i = sdet[t];
        float4 b = g_boxes[img][i];
        int o = img * DETN + t;
        out[o * 4 + 0] = b.x;
        out[o * 4 + 1] = b.y;
        out[o * 4 + 2] = b.z;
        out[o * 4 + 3] = b.w;
        out[BB * DETN * 4 + o] = sflag[t] ? g_scores[img][i] : -1.0f;
        out[BB * DETN * 5 + o] = (float)g_labels[img][i];
    }
}

// ---------------- launch ----------------
extern "C" void kernel_launch(void* const* d_in, const int* in_sizes, int n_in,
                              void* d_out, int out_size) {
    const float* label = (const float*)d_in[0];
    const float* bbox  = (const float*)d_in[1];
    const float* props = (const float*)d_in[2];
    float* out = (float*)d_out;

    k_init<<<512, 256>>>();
    k_scorekey<<<dim3(500, BB), 256>>>(label, bbox, props);
    k_select16<<<BB, 256>>>();
    k_compact<<<dim3(160, BB), 256>>>();
    k_sortdecode<<<BB, 1024>>>(bbox, props);
    k_nmsout<<<BB, 32>>>(out);
}